// round 2
// baseline (speedup 1.0000x reference)
#include <cuda_runtime.h>

// Sparsemax over rows of (B, 256) fp32 via Michelot's simplex-projection
// algorithm (exact, sort-free).
//
// One warp per row. Each lane holds 8 consecutive values (2x float4).
// Iterate: tau = (sum_active - 1)/count_active; active = {z > tau};
// stop when count stops shrinking (monotone => exact fixed point).

static constexpr int D = 256;

__global__ void __launch_bounds__(256) sparsemax_kernel(
    const float* __restrict__ in, float* __restrict__ out, int B)
{
    const int warp_id = (blockIdx.x * blockDim.x + threadIdx.x) >> 5;
    const int lane = threadIdx.x & 31;
    if (warp_id >= B) return;

    const float4* row_in = reinterpret_cast<const float4*>(in + (size_t)warp_id * D);
    float4 a = row_in[lane];        // bytes [lane*16, lane*16+16) -> coalesced 512B
    float4 b = row_in[lane + 32];   // second 512B half of the 1024B row

    float v[8] = {a.x, a.y, a.z, a.w, b.x, b.y, b.z, b.w};

    float tau = -__int_as_float(0x7f800000);  // -inf: all elements active first pass
    int k_prev = -1;

    #pragma unroll 1
    for (int iter = 0; iter < 64; ++iter) {
        float s = 0.0f;
        int c = 0;
        #pragma unroll
        for (int j = 0; j < 8; ++j) {
            bool act = v[j] > tau;
            s += act ? v[j] : 0.0f;
            c += act ? 1 : 0;
        }
        // Butterfly reduction across the warp (sum + count).
        #pragma unroll
        for (int off = 16; off > 0; off >>= 1) {
            s += __shfl_xor_sync(0xffffffffu, s, off);
            c += __shfl_xor_sync(0xffffffffu, c, off);
        }
        if (c == k_prev) break;       // active set stable -> tau is exact
        k_prev = c;
        tau = (s - 1.0f) / (float)c;  // c >= 1 always (max element stays active)
    }

    float4 oa, ob;
    oa.x = fmaxf(v[0] - tau, 0.0f);
    oa.y = fmaxf(v[1] - tau, 0.0f);
    oa.z = fmaxf(v[2] - tau, 0.0f);
    oa.w = fmaxf(v[3] - tau, 0.0f);
    ob.x = fmaxf(v[4] - tau, 0.0f);
    ob.y = fmaxf(v[5] - tau, 0.0f);
    ob.z = fmaxf(v[6] - tau, 0.0f);
    ob.w = fmaxf(v[7] - tau, 0.0f);

    float4* row_out = reinterpret_cast<float4*>(out + (size_t)warp_id * D);
    row_out[lane] = oa;
    row_out[lane + 32] = ob;
}

extern "C" void kernel_launch(void* const* d_in, const int* in_sizes, int n_in,
                              void* d_out, int out_size)
{
    const float* logits = (const float*)d_in[0];
    float* out = (float*)d_out;
    const int B = in_sizes[0] / D;

    const int warps_per_block = 8;               // 256 threads
    const int rows_per_block = warps_per_block;  // 1 row per warp
    const int grid = (B + rows_per_block - 1) / rows_per_block;
    sparsemax_kernel<<<grid, 256>>>(logits, out, B);
}

// round 3
// speedup vs baseline: 1.7524x; 1.7524x over previous
#include <cuda_runtime.h>

// Sparsemax over rows of (B, 256) fp32.
// Michelot simplex projection, warm-started at tau0 = max(z) - 1
// (valid superset: tau* >= z_max - 1 since p_max <= 1).
// Fixed-point int arithmetic so warp reductions use single-instruction
// __reduce_add_sync / __reduce_max_sync (REDUX) instead of shuffle trees.

static constexpr int   D         = 256;
static constexpr int   ISCALE    = 1 << 20;
static constexpr float SCALE     = (float)ISCALE;          // 2^20
static constexpr float INV_SCALE = 1.0f / (float)(1 << 20);

__global__ void __launch_bounds__(256) sparsemax_kernel(
    const float* __restrict__ in, float* __restrict__ out, int B)
{
    const int warp_id = (blockIdx.x * blockDim.x + threadIdx.x) >> 5;
    const int lane = threadIdx.x & 31;
    if (warp_id >= B) return;

    const float4* row_in = reinterpret_cast<const float4*>(in + (size_t)warp_id * D);
    float4 a = row_in[lane];        // coalesced 512B
    float4 b = row_in[lane + 32];   // second half of the 1KB row

    float v[8] = {a.x, a.y, a.z, a.w, b.x, b.y, b.z, b.w};

    // Fixed-point copy (monotone map; sums over <=256 elems fit int32).
    int iv[8];
    #pragma unroll
    for (int j = 0; j < 8; ++j) iv[j] = __float2int_rn(v[j] * SCALE);

    // Warm start: tau0 = max - 1.0 (guaranteed superset of the support).
    int mx = iv[0];
    #pragma unroll
    for (int j = 1; j < 8; ++j) mx = max(mx, iv[j]);
    mx = __reduce_max_sync(0xffffffffu, mx);

    int tau_i = mx - ISCALE;
    int s = 0, c = 1, cprev = -1;

    #pragma unroll 1
    for (int it = 0; it < 32; ++it) {
        s = 0; c = 0;
        #pragma unroll
        for (int j = 0; j < 8; ++j) {
            bool act = iv[j] > tau_i;
            s += act ? iv[j] : 0;
            c += (int)act;
        }
        s = __reduce_add_sync(0xffffffffu, s);  // REDUX.SUM
        c = __reduce_add_sync(0xffffffffu, c);  // REDUX.SUM
        if (c == cprev) break;                  // active set stable -> converged
        cprev = c;
        // tau = (sum - 1)/c, rounded DOWN in fixed point to keep the
        // active set a superset of the true support.
        float tf = ((float)s * INV_SCALE - 1.0f) * __frcp_rn((float)c);
        tau_i = __float2int_rd(tf * SCALE);
    }

    // Final tau from the stable (s, c); full-precision divide once.
    const float tau_f = ((float)s * INV_SCALE - 1.0f) / (float)c;

    float4 oa, ob;
    oa.x = fmaxf(v[0] - tau_f, 0.0f);
    oa.y = fmaxf(v[1] - tau_f, 0.0f);
    oa.z = fmaxf(v[2] - tau_f, 0.0f);
    oa.w = fmaxf(v[3] - tau_f, 0.0f);
    ob.x = fmaxf(v[4] - tau_f, 0.0f);
    ob.y = fmaxf(v[5] - tau_f, 0.0f);
    ob.z = fmaxf(v[6] - tau_f, 0.0f);
    ob.w = fmaxf(v[7] - tau_f, 0.0f);

    float4* row_out = reinterpret_cast<float4*>(out + (size_t)warp_id * D);
    row_out[lane] = oa;
    row_out[lane + 32] = ob;
}

extern "C" void kernel_launch(void* const* d_in, const int* in_sizes, int n_in,
                              void* d_out, int out_size)
{
    const float* logits = (const float*)d_in[0];
    float* out = (float*)d_out;
    const int B = in_sizes[0] / D;

    const int grid = (B + 7) / 8;   // 8 warps (rows) per 256-thread block
    sparsemax_kernel<<<grid, 256>>>(logits, out, B);
}